// round 16
// baseline (speedup 1.0000x reference)
#include <cuda_runtime.h>
#include <cuda_bf16.h>
#include <math.h>
#include <stdint.h>

#define SV 2048
#define SA 512
#define S_TOT 2560
#define D_MODEL 1024
#define NH 16
#define DH 64
#define FF 4096
#define NL 2
#define LOG2E 1.4426950408889634f

__device__ __align__(16) float g_x[S_TOT * D_MODEL];
__device__ __align__(16) float g_a[S_TOT * D_MODEL];
__device__ __align__(16) float g_q[S_TOT * D_MODEL];
__device__ __align__(16) float g_k[S_TOT * D_MODEL];
__device__ __align__(16) float g_v[S_TOT * D_MODEL];
__device__ __align__(16) float g_vt[D_MODEL * S_TOT];
__device__ __align__(16) float g_o[S_TOT * D_MODEL];
__device__ __align__(16) float g_h[S_TOT * FF];
__device__ __align__(16) float g_m6[2 * 6 * D_MODEL];
__device__ __align__(16) uint32_t g_wqt[NL * 2 * D_MODEL * D_MODEL];
__device__ __align__(16) uint32_t g_wkt[NL * 2 * D_MODEL * D_MODEL];
__device__ __align__(16) uint32_t g_wvt[NL * 2 * D_MODEL * D_MODEL];
__device__ __align__(16) uint32_t g_wot[NL * 2 * D_MODEL * D_MODEL];
__device__ __align__(16) uint32_t g_w1t[(size_t)NL * 2 * D_MODEL * FF];
__device__ __align__(16) uint32_t g_w2t[(size_t)NL * 2 * FF * D_MODEL];

struct GemmArgs {
    const uint32_t* Ah;
    size_t amid;
    const uint32_t* Bth[3];
    size_t bmid;
    size_t westride;
    const float* bias[3];
    size_t bestride;
    void* C[3];
    size_t cmid;
    const float* res;
    const float* m6;
    int gidx;
    int K, ldc;
};

__device__ __forceinline__ void mma16(float* d, const uint32_t* a, const uint32_t* b) {
    asm volatile("mma.sync.aligned.m16n8k16.row.col.f32.bf16.bf16.f32 "
        "{%0,%1,%2,%3}, {%4,%5,%6,%7}, {%8,%9}, {%0,%1,%2,%3};"
        : "+f"(d[0]), "+f"(d[1]), "+f"(d[2]), "+f"(d[3])
        : "r"(a[0]), "r"(a[1]), "r"(a[2]), "r"(a[3]), "r"(b[0]), "r"(b[1]));
}
__device__ __forceinline__ void ldsm_x4(uint32_t* r, uint32_t addr) {
    asm volatile("ldmatrix.sync.aligned.m8n8.x4.shared.b16 {%0,%1,%2,%3}, [%4];"
        : "=r"(r[0]), "=r"(r[1]), "=r"(r[2]), "=r"(r[3]) : "r"(addr));
}
__device__ __forceinline__ void cpasync16(uint32_t saddr, const void* g) {
    asm volatile("cp.async.cg.shared.global [%0], [%1], 16;" :: "r"(saddr), "l"(g));
}
__device__ __forceinline__ void cp_commit() {
    asm volatile("cp.async.commit_group;");
}
__device__ __forceinline__ void cp_wait0() {
    asm volatile("cp.async.wait_group 0;");
}

__device__ __forceinline__ float fexp2(float x) {
    x = fmaxf(x, -126.f);
    float fl = floorf(x);
    float f = x - fl;
    float p = 1.54035304e-4f;
    p = fmaf(p, f, 1.33335581e-3f);
    p = fmaf(p, f, 9.61812911e-3f);
    p = fmaf(p, f, 5.55041087e-2f);
    p = fmaf(p, f, 2.40226507e-1f);
    p = fmaf(p, f, 6.93147181e-1f);
    p = fmaf(p, f, 1.0f);
    return p * __int_as_float(((int)fl + 127) << 23);
}

__device__ __forceinline__ uint32_t pack_bf2(float a, float b) {
    __nv_bfloat162 t = __floats2bfloat162_rn(a, b);
    return *(const uint32_t*)&t;
}
__device__ __forceinline__ void split2(float a, float b, uint32_t& hi, uint32_t& mid) {
    hi = pack_bf2(a, b);
    __nv_bfloat162* H = (__nv_bfloat162*)&hi;
    mid = pack_bf2(a - __bfloat162float(H->x), b - __bfloat162float(H->y));
}

__device__ __forceinline__ void blockReduce2(float& s, float& ss) {
    __shared__ float bufs[8], bufss[8];
    #pragma unroll
    for (int o = 16; o; o >>= 1) {
        s += __shfl_xor_sync(~0u, s, o); ss += __shfl_xor_sync(~0u, ss, o);
    }
    int w = threadIdx.x >> 5;
    if ((threadIdx.x & 31) == 0) { bufs[w] = s; bufss[w] = ss; }
    __syncthreads();
    if (threadIdx.x < 32) {
        s = (threadIdx.x < 8) ? bufs[threadIdx.x] : 0.f;
        ss = (threadIdx.x < 8) ? bufss[threadIdx.x] : 0.f;
        #pragma unroll
        for (int o = 4; o; o >>= 1) {
            s += __shfl_xor_sync(~0u, s, o); ss += __shfl_xor_sync(~0u, ss, o);
        }
        if (threadIdx.x == 0) { bufs[0] = s; bufss[0] = ss; }
    }
    __syncthreads();
    s = bufs[0]; ss = bufss[0];
}

__global__ void m6_kernel(const float* __restrict__ mod, const float* __restrict__ vt,
                          const float* __restrict__ at, float* __restrict__ m6, int l) {
    int idx = blockIdx.x * blockDim.x + threadIdx.x;
    if (idx >= 2 * 6 * D_MODEL) return;
    int e = idx / (6 * D_MODEL);
    int rem = idx % (6 * D_MODEL);
    m6[idx] = mod[((size_t)(e * NL + l) * 6) * D_MODEL + rem] + (e ? at[rem] : vt[rem]);
}

__global__ void __launch_bounds__(256) lnmod_kernel(const float* __restrict__ x, uint32_t* __restrict__ a,
                                                    const float* __restrict__ m6, int jsh, int jsc) {
    int row = blockIdx.x;
    int e = (row >= SV) ? 1 : 0;
    const float4* shv4 = (const float4*)(m6 + (size_t)(e * 6 + jsh) * D_MODEL);
    const float4* scv4 = (const float4*)(m6 + (size_t)(e * 6 + jsc) * D_MODEL);
    float4 v = ((const float4*)(x + (size_t)row * D_MODEL))[threadIdx.x];
    float s = v.x + v.y + v.z + v.w;
    float ss = v.x * v.x + v.y * v.y + v.z * v.z + v.w * v.w;
    blockReduce2(s, ss);
    float mu = s * (1.f / D_MODEL);
    float var = ss * (1.f / D_MODEL) - mu * mu;
    float r = rsqrtf(var + 1e-6f);
    float4 sh = shv4[threadIdx.x], sc = scv4[threadIdx.x];
    float o0 = (v.x - mu) * r * (1.f + sc.x) + sh.x;
    float o1 = (v.y - mu) * r * (1.f + sc.y) + sh.y;
    float o2 = (v.z - mu) * r * (1.f + sc.z) + sh.z;
    float o3 = (v.w - mu) * r * (1.f + sc.w) + sh.w;
    uint32_t h01, m01, h23, m23;
    split2(o0, o1, h01, m01);
    split2(o2, o3, h23, m23);
    const size_t MID = (size_t)S_TOT * D_MODEL / 2;
    size_t w = (size_t)row * (D_MODEL / 2) + threadIdx.x * 2;
    a[w] = h01; a[w + 1] = h23;
    a[MID + w] = m01; a[MID + w + 1] = m23;
}

__global__ void __launch_bounds__(256) rmsrope_kernel(float* __restrict__ qb, float* __restrict__ kb,
                                                      const float* __restrict__ gq, const float* __restrict__ gk,
                                                      const float* __restrict__ vfreq, const float* __restrict__ afreq,
                                                      int l) {
    int bid = blockIdx.x;
    int isk = (bid >= S_TOT);
    int row = isk ? bid - S_TOT : bid;
    float* q = isk ? kb : qb;
    const float* gbase = isk ? gk : gq;
    int e = (row >= SV) ? 1 : 0;
    int pos = e ? row - SV : row;
    const float* fr = e ? (afreq + (size_t)pos * (DH / 2)) : (vfreq + (size_t)pos * (DH / 2));
    const float* g = gbase + (size_t)(e * NL + l) * D_MODEL;
    float4 v = ((const float4*)(q + (size_t)row * D_MODEL))[threadIdx.x];
    float ss = v.x * v.x + v.y * v.y + v.z * v.z + v.w * v.w, dummy = 0.f;
    blockReduce2(ss, dummy);
    float r = rsqrtf(ss * (1.f / D_MODEL) + 1e-6f);
    float4 gv = ((const float4*)g)[threadIdx.x];
    int d0 = threadIdx.x * 4;
    int j0 = (d0 & (DH - 1)) >> 1, j1 = j0 + 1;
    float c0 = cosf(fr[j0]), s0 = sinf(fr[j0]);
    float c1 = cosf(fr[j1]), s1 = sinf(fr[j1]);
    float xe0 = v.x * r * gv.x, xo0 = v.y * r * gv.y;
    float xe1 = v.z * r * gv.z, xo1 = v.w * r * gv.w;
    float4 o;
    o.x = xe0 * c0 - xo0 * s0; o.y = xe0 * s0 + xo0 * c0;
    o.z = xe1 * c1 - xo1 * s1; o.w = xe1 * s1 + xo1 * c1;
    ((float4*)(q + (size_t)row * D_MODEL))[threadIdx.x] = o;
}

__global__ void __launch_bounds__(256) transpose_kernel(const float* __restrict__ src, float* __restrict__ dst,
                                                        int R, int C, size_t msize) {
    __shared__ float t[32][33];
    src += blockIdx.z * msize;
    dst += blockIdx.z * msize;
    int bx = blockIdx.x * 32, by = blockIdx.y * 32;
    for (int i = threadIdx.y; i < 32; i += 8)
        t[i][threadIdx.x] = src[(size_t)(by + i) * C + bx + threadIdx.x];
    __syncthreads();
    for (int i = threadIdx.y; i < 32; i += 8)
        dst[(size_t)(bx + i) * R + by + threadIdx.x] = t[threadIdx.x][i];
}

// transpose + bf16 split, coalesced stores: tile 64(R) x 32(C)
__global__ void __launch_bounds__(256) transposeW_kernel(const float* __restrict__ src, uint32_t* __restrict__ dst,
                                                         int R, int C, size_t min_, size_t mout, size_t midoff) {
    __shared__ float t[64][33];
    src += blockIdx.z * min_;
    dst += blockIdx.z * mout;
    int bx = blockIdx.x * 32, by = blockIdx.y * 64;
    int tx = threadIdx.x, ty = threadIdx.y;
    #pragma unroll
    for (int i = ty; i < 64; i += 8)
        t[i][tx] = src[(size_t)(by + i) * C + bx + tx];
    __syncthreads();
    #pragma unroll
    for (int i = ty; i < 32; i += 8) {
        float v0 = t[2 * tx][i], v1 = t[2 * tx + 1][i];
        uint32_t hi, mid;
        split2(v0, v1, hi, mid);
        size_t w = (size_t)(bx + i) * (R >> 1) + (by >> 1) + tx;
        dst[w] = hi;
        dst[midoff + w] = mid;
    }
}

// ---------------- flash attention: 128-row Q tile, 256 threads, dynamic smem ----------------
#define FST 36
#define FQW (128 * FST)
#define FKW (64 * FST)
__global__ void __launch_bounds__(256) flash_kernel(
    const float* __restrict__ Q, const float* __restrict__ K,
    const float* __restrict__ Vt, uint32_t* __restrict__ O) {
    extern __shared__ __align__(16) uint32_t fsm[];
    uint32_t* sQh = fsm;
    uint32_t* sQm = fsm + FQW;
    uint32_t* sKh = fsm + 2 * FQW;
    uint32_t* sKm = fsm + 2 * FQW + FKW;
    uint32_t* sVh = fsm + 2 * FQW + 2 * FKW;
    uint32_t* sVm = fsm + 2 * FQW + 3 * FKW;
    int h = blockIdx.x;
    int q0 = blockIdx.y * 128;
    int tid = threadIdx.x, wid = tid >> 5, lane = tid & 31;
    int r = lane >> 2, cq = lane & 3;

    uint32_t bQh = (uint32_t)__cvta_generic_to_shared(sQh);
    uint32_t bQm = (uint32_t)__cvta_generic_to_shared(sQm);
    uint32_t bKh = (uint32_t)__cvta_generic_to_shared(sKh);
    uint32_t bKm = (uint32_t)__cvta_generic_to_shared(sKm);
    uint32_t bVh = (uint32_t)__cvta_generic_to_shared(sVh);
    uint32_t bVm = (uint32_t)__cvta_generic_to_shared(sVm);
    uint32_t aoff = ((wid * 16 + (lane & 15)) * FST + ((lane >> 4) << 2)) * 4;
    uint32_t boff = ((((lane & 7) + ((lane >> 4) << 3)) * FST) + (((lane >> 3) & 1) << 2)) * 4;

    // Q tile: 128 rows, scale 1/8 folded in
    #pragma unroll
    for (int i = 0; i < 8; i++) {
        int idx = tid + i * 256;
        int row = idx >> 4, c4 = idx & 15;
        float4 f = *(const float4*)(Q + (size_t)(q0 + row) * D_MODEL + h * DH + c4 * 4);
        f.x *= 0.125f; f.y *= 0.125f; f.z *= 0.125f; f.w *= 0.125f;
        uint32_t h01, m01, h23, m23;
        split2(f.x, f.y, h01, m01);
        split2(f.z, f.w, h23, m23);
        int o2 = row * FST + c4 * 2;
        sQh[o2] = h01; sQh[o2 + 1] = h23;
        sQm[o2] = m01; sQm[o2 + 1] = m23;
    }

    int row0 = q0 + wid * 16 + r, row1 = row0 + 8;
    float mx0 = -1e30f, mx1 = -1e30f, l0 = 0.f, l1 = 0.f;
    float oa[8][4];
    #pragma unroll
    for (int j = 0; j < 8; j++)
        #pragma unroll
        for (int t = 0; t < 4; t++) oa[j][t] = 0.f;

    int kend = (q0 < SV) ? SV : (q0 + 128);
    for (int kb = 0; kb < kend; kb += 64) {
        __syncthreads();
        #pragma unroll
        for (int i = 0; i < 8; i++) {
            int idx = tid + i * 256;
            const float* src;
            uint32_t *dh_, *dm_;
            int row, c4;
            if (idx < 1024) {
                row = idx >> 4; c4 = idx & 15;
                src = K + (size_t)(kb + row) * D_MODEL + h * DH + c4 * 4;
                dh_ = sKh; dm_ = sKm;
            } else {
                int jj = idx - 1024;
                row = jj >> 4; c4 = jj & 15;
                src = Vt + (size_t)(h * DH + row) * S_TOT + kb + c4 * 4;
                dh_ = sVh; dm_ = sVm;
            }
            float4 f = *(const float4*)src;
            uint32_t h01, m01, h23, m23;
            split2(f.x, f.y, h01, m01);
            split2(f.z, f.w, h23, m23);
            int o2 = row * FST + c4 * 2;
            dh_[o2] = h01; dh_[o2 + 1] = h23;
            dm_[o2] = m01; dm_[o2 + 1] = m23;
        }
        __syncthreads();

        float s[8][4];
        #pragma unroll
        for (int j = 0; j < 8; j++)
            #pragma unroll
            for (int t = 0; t < 4; t++) s[j][t] = 0.f;
        #pragma unroll
        for (int k16 = 0; k16 < 4; k16++) {
            int kwB = k16 * 32;
            uint32_t ah[4], am[4];
            ldsm_x4(ah, bQh + aoff + kwB);
            ldsm_x4(am, bQm + aoff + kwB);
            #pragma unroll
            for (int jp = 0; jp < 8; jp += 2) {
                uint32_t bh4[4], bm4[4];
                ldsm_x4(bh4, bKh + boff + jp * 8 * FST * 4 + kwB);
                ldsm_x4(bm4, bKm + boff + jp * 8 * FST * 4 + kwB);
                mma16(s[jp], ah, bh4);
                mma16(s[jp], am, bh4);
                mma16(s[jp], ah, bm4);
                mma16(s[jp + 1], ah, bh4 + 2);
                mma16(s[jp + 1], am, bh4 + 2);
                mma16(s[jp + 1], ah, bm4 + 2);
            }
        }
        if (kb >= SV) {
            #pragma unroll
            for (int j = 0; j < 8; j++) {
                int key = kb + j * 8 + 2 * cq;
                if (key > row0) s[j][0] = -1e30f;
                if (key + 1 > row0) s[j][1] = -1e30f;
                if (key > row1) s[j][2] = -1e30f;
                if (key + 1 > row1) s[j][3] = -1e30f;
            }
        }
        float tm0 = -1e30f, tm1 = -1e30f;
        #pragma unroll
        for (int j = 0; j < 8; j++) {
            tm0 = fmaxf(tm0, fmaxf(s[j][0], s[j][1]));
            tm1 = fmaxf(tm1, fmaxf(s[j][2], s[j][3]));
        }
        tm0 = fmaxf(tm0, __shfl_xor_sync(~0u, tm0, 1));
        tm0 = fmaxf(tm0, __shfl_xor_sync(~0u, tm0, 2));
        tm1 = fmaxf(tm1, __shfl_xor_sync(~0u, tm1, 1));
        tm1 = fmaxf(tm1, __shfl_xor_sync(~0u, tm1, 2));
        float mn0 = fmaxf(mx0, tm0), mn1 = fmaxf(mx1, tm1);
        float corr0 = fexp2((mx0 - mn0) * LOG2E);
        float corr1 = fexp2((mx1 - mn1) * LOG2E);
        mx0 = mn0; mx1 = mn1;
        float ps0 = 0.f, ps1 = 0.f;
        #pragma unroll
        for (int j = 0; j < 8; j++) {
            s[j][0] = fexp2((s[j][0] - mn0) * LOG2E);
            s[j][1] = fexp2((s[j][1] - mn0) * LOG2E);
            s[j][2] = fexp2((s[j][2] - mn1) * LOG2E);
            s[j][3] = fexp2((s[j][3] - mn1) * LOG2E);
            ps0 += s[j][0] + s[j][1];
            ps1 += s[j][2] + s[j][3];
        }
        ps0 += __shfl_xor_sync(~0u, ps0, 1); ps0 += __shfl_xor_sync(~0u, ps0, 2);
        ps1 += __shfl_xor_sync(~0u, ps1, 1); ps1 += __shfl_xor_sync(~0u, ps1, 2);
        l0 = l0 * corr0 + ps0;
        l1 = l1 * corr1 + ps1;
        #pragma unroll
        for (int j = 0; j < 8; j++) {
            oa[j][0] *= corr0; oa[j][1] *= corr0;
            oa[j][2] *= corr1; oa[j][3] *= corr1;
        }
        #pragma unroll
        for (int j2 = 0; j2 < 4; j2++) {
            int t0 = 2 * j2, t1 = 2 * j2 + 1;
            uint32_t pah[4], pam[4];
            split2(s[t0][0], s[t0][1], pah[0], pam[0]);
            split2(s[t0][2], s[t0][3], pah[1], pam[1]);
            split2(s[t1][0], s[t1][1], pah[2], pam[2]);
            split2(s[t1][2], s[t1][3], pah[3], pam[3]);
            int kwB = j2 * 32;
            #pragma unroll
            for (int jp = 0; jp < 8; jp += 2) {
                uint32_t bh4[4], bm4[4];
                ldsm_x4(bh4, bVh + boff + jp * 8 * FST * 4 + kwB);
                ldsm_x4(bm4, bVm + boff + jp * 8 * FST * 4 + kwB);
                mma16(oa[jp], pah, bh4);
                mma16(oa[jp], pam, bh4);
                mma16(oa[jp], pah, bm4);
                mma16(oa[jp + 1], pah, bh4 + 2);
                mma16(oa[jp + 1], pam, bh4 + 2);
                mma16(oa[jp + 1], pah, bm4 + 2);
            }
        }
    }

    const size_t OMID = (size_t)S_TOT * D_MODEL / 2;
    float inv0 = 1.f / l0, inv1 = 1.f / l1;
    #pragma unroll
    for (int jn = 0; jn < 8; jn++) {
        int col = h * DH + jn * 8 + cq * 2;
        uint32_t hi0, mi0, hi1, mi1;
        split2(oa[jn][0] * inv0, oa[jn][1] * inv0, hi0, mi0);
        split2(oa[jn][2] * inv1, oa[jn][3] * inv1, hi1, mi1);
        size_t w0 = (size_t)row0 * (D_MODEL / 2) + (col >> 1);
        size_t w1 = (size_t)row1 * (D_MODEL / 2) + (col >> 1);
        O[w0] = hi0; O[OMID + w0] = mi0;
        O[w1] = hi1; O[OMID + w1] = mi1;
    }
}

// ---------- merged GEMM: pre-split inputs, cp.async staging, LDSM fragments ----------
template <int EPI, int BN>
__global__ void __launch_bounds__((BN == 128) ? 256 : 128) tgemm(GemmArgs args) {
    constexpr int THREADS = (BN == 128) ? 256 : 128;
    constexpr int WX = BN / 32;
    constexpr int AHI = 0, AMI = 2560, BHIo = 5120, BMIo = 5120 + BN * 20;
    constexpr int STG = 5120 + BN * 40;
    constexpr int NPF = (1024 + BN * 8) / THREADS;

    extern __shared__ uint32_t smw[];
    int tid = threadIdx.x;
    int wid = tid >> 5, lane = tid & 31;
    int wy = wid / WX, wx = wid % WX;
    int r = lane >> 2, cq = lane & 3;
    int z = blockIdx.z;
    int e = (blockIdx.y * 128 >= SV) ? 1 : 0;
    int K = args.K;
    int ldw = K >> 1;

    uint32_t sbase = (uint32_t)__cvta_generic_to_shared(smw);
    uint32_t aoff = ((wy * 64 + (lane & 15)) * 20 + ((lane >> 4) << 2)) * 4;
    uint32_t boff = ((wx * 32 + (lane & 7) + ((lane >> 4) << 3)) * 20 + (((lane >> 3) & 1) << 2)) * 4;

    const uint32_t* Ahi = args.Ah + (size_t)blockIdx.y * 128 * ldw;
    const uint32_t* Bhi = args.Bth[z] + (size_t)e * args.westride + (size_t)blockIdx.x * BN * ldw;
    size_t amid = args.amid, bmid = args.bmid;
    const float* bias = args.bias[z] + (size_t)e * args.bestride;
    const float* gate = (EPI == 2) ? (args.m6 + (size_t)(e * 6 + args.gidx) * D_MODEL) : nullptr;
    int ldc = args.ldc;

    float acc[4][4][4];
    #pragma unroll
    for (int i = 0; i < 4; i++)
        #pragma unroll
        for (int j = 0; j < 4; j++)
            #pragma unroll
            for (int t = 0; t < 4; t++) acc[i][j][t] = 0.f;

    auto issueLoads = [&](int c, int s) {
        uint32_t base = sbase + s * STG * 4;
        #pragma unroll
        for (int t = 0; t < NPF; t++) {
            int idx = tid + t * THREADS;
            const uint32_t* src;
            int plane, i2;
            if (idx < 1024) {
                int p = idx >> 9;
                i2 = idx & 511;
                src = Ahi + (p ? amid : 0) + (size_t)(i2 >> 2) * ldw + c * 16 + (i2 & 3) * 4;
                plane = p ? AMI : AHI;
            } else {
                int bidx = idx - 1024;
                int p = (bidx >= BN * 4) ? 1 : 0;
                i2 = bidx - p * BN * 4;
                src = Bhi + (p ? bmid : 0) + (size_t)(i2 >> 2) * ldw + c * 16 + (i2 & 3) * 4;
                plane = p ? BMIo : BHIo;
            }
            cpasync16(base + (plane + (i2 >> 2) * 20 + (i2 & 3) * 4) * 4, src);
        }
        cp_commit();
    };
    auto compute = [&](int s) {
        uint32_t stb = sbase + s * STG * 4;
        #pragma unroll
        for (int k16 = 0; k16 < 2; k16++) {
            int kwB = k16 * 32;
            uint32_t ah[4][4], am[4][4], bh[2][4], bm[2][4];
            #pragma unroll
            for (int i = 0; i < 4; i++) {
                ldsm_x4(ah[i], stb + aoff + i * 16 * 20 * 4 + kwB);
                ldsm_x4(am[i], stb + AMI * 4 + aoff + i * 16 * 20 * 4 + kwB);
            }
            #pragma unroll
            for (int jp = 0; jp < 2; jp++) {
                ldsm_x4(bh[jp], stb + BHIo * 4 + boff + jp * 16 * 20 * 4 + kwB);
                ldsm_x4(bm[jp], stb + BMIo * 4 + boff + jp * 16 * 20 * 4 + kwB);
            }
            #pragma unroll
            for (int i = 0; i < 4; i++)
                #pragma unroll
                for (int j = 0; j < 4; j++)
                    mma16(acc[i][j], ah[i], bh[j >> 1] + (j & 1) * 2);
            #pragma unroll
            for (int i = 0; i < 4; i++)
                #pragma unroll
                for (int j = 0; j < 4; j++)
                    mma16(acc[i][j], am[i], bh[j >> 1] + (j & 1) * 2);
            #pragma unroll
            for (int i = 0; i < 4; i++)
                #pragma unroll
                for (int j = 0; j < 4; j++)
                    mma16(acc[i][j], ah[i], bm[j >> 1] + (j & 1) * 2);
        }
    };

    issueLoads(0, 0);
    cp_wait0();
    __syncthreads();
    int NC = K >> 5;
    for (int c = 0; c < NC; c++) {
        if (c + 1 < NC) issueLoads(c + 1, (c + 1) & 1);
        compute(c & 1);
        if (c + 1 < NC) cp_wait0();
        __syncthreads();
    }

    int rowb = blockIdx.y * 128 + wy * 64;
    int colb = blockIdx.x * BN + wx * 32;
    #pragma unroll
    for (int i = 0; i < 4; i++) {
        #pragma unroll
        for (int j = 0; j < 4; j++) {
            int col = colb + j * 8 + cq * 2;
            #pragma unroll
            for (int h = 0; h < 2; h++) {
                int row = rowb + i * 16 + r + h * 8;
                float v0 = acc[i][j][h * 2], v1 = acc[i][j][h * 2 + 1];
                v0 += bias[col]; v1 += bias[col + 1];
                if (EPI == 1) {
                    float t0 = v0, t1 = v1;
                    v0 = 0.5f * t0 * (1.f + tanhf(0.7978845608028654f * (t0 + 0.044715f * t0 * t0 * t0)));
                    v1 = 0.5f * t1 * (1.f + tanhf(0.7978845608028654f * (t1 + 0.044715f * t1 * t1 * t1)));
                    uint32_t hi, mid;
                    split2(v0, v1, hi, mid);
                    uint32_t* Ch = (uint32_t*)args.C[z];
                    size_t w = (size_t)row * (ldc >> 1) + (col >> 1);
                    Ch[w] = hi;
                    Ch[args.cmid + w] = mid;
                } else {
                    if (EPI == 2) {
                        float2 rv = *(const float2*)(args.res + (size_t)row * ldc + col);
                        v0 = rv.x + gate[col] * v0;
                        v1 = rv.y + gate[col + 1] * v1;
                    }
                    float2 ov; ov.x = v0; ov.y = v1;
                    *(float2*)((float*)args.C[z] + (size_t)row * ldc + col) = ov;
                }
            }
        }
    }
}

extern "C" void kernel_launch(void* const* d_in, const int* in_sizes, int n_in,
                              void* d_out, int out_size) {
    const float* video = (const float*)d_in[0];
    const float* action = (const float*)d_in[1];
    const float* vfreq = (const float*)d_in[2];
    const float* afreq = (const float*)d_in[3];
    const float* vtmod = (const float*)d_in[4];
    const float* atmod = (const float*)d_in[5];
    const float* Wq = (const float*)d_in[6];
    const float* Wk = (const float*)d_in[7];
    const float* Wv = (const float*)d_in[8];
    const float* Wo = (const float*)d_in[9];
    const float* bq = (const float*)d_in[10];
    const float* bk = (const float*)d_in[11];
    const float* bv = (const float*)d_in[12];
    const float* bo = (const float*)d_in[13];
    const float* gq = (const float*)d_in[14];
    const float* gk = (const float*)d_in[15];
    const float* mod = (const float*)d_in[16];
    const float* W1 = (const float*)d_in[17];
    const float* b1 = (const float*)d_in[18];
    const float* W2 = (const float*)d_in[19];
    const float* b2 = (const float*)d_in[20];
    float* out = (float*)d_out;

    float *x, *a, *q, *k, *v, *vt, *o, *hbuf, *m6;
    uint32_t *wqt, *wkt, *wvt, *wot, *w1t, *w2t;
    cudaGetSymbolAddress((void**)&x, g_x);
    cudaGetSymbolAddress((void**)&a, g_a);
    cudaGetSymbolAddress((void**)&q, g_q);
    cudaGetSymbolAddress((void**)&k, g_k);
    cudaGetSymbolAddress((void**)&v, g_v);
    cudaGetSymbolAddress((void**)&vt, g_vt);
    cudaGetSymbolAddress((void**)&o, g_o);
    cudaGetSymbolAddress((void**)&hbuf, g_h);
    cudaGetSymbolAddress((void**)&m6, g_m6);
    cudaGetSymbolAddress((void**)&wqt, g_wqt);
    cudaGetSymbolAddress((void**)&wkt, g_wkt);
    cudaGetSymbolAddress((void**)&wvt, g_wvt);
    cudaGetSymbolAddress((void**)&wot, g_wot);
    cudaGetSymbolAddress((void**)&w1t, g_w1t);
    cudaGetSymbolAddress((void**)&w2t, g_w2t);

    const int SM128 = (5120 + 128 * 40) * 2 * 4;
    const int SM64  = (5120 + 64 * 40) * 2 * 4;
    const int SMFL  = (2 * FQW + 4 * FKW) * 4;   // 73728 B
    cudaFuncSetAttribute(tgemm<0, 128>, cudaFuncAttributeMaxDynamicSharedMemorySize, SM128);
    cudaFuncSetAttribute(tgemm<1, 128>, cudaFuncAttributeMaxDynamicSharedMemorySize, SM128);
    cudaFuncSetAttribute(tgemm<2, 64>, cudaFuncAttributeMaxDynamicSharedMemorySize, SM64);
    cudaFuncSetAttribute(flash_kernel, cudaFuncAttributeMaxDynamicSharedMemorySize, SMFL);

    dim3 tb(32, 8);
    {
        size_t mdd = (size_t)D_MODEL * D_MODEL;
        dim3 gdd(D_MODEL / 32, D_MODEL / 64, 4);
        transposeW_kernel<<<gdd, tb>>>(Wq, wqt, D_MODEL, D_MODEL, mdd, mdd, mdd / 2);
        transposeW_kernel<<<gdd, tb>>>(Wk, wkt, D_MODEL, D_MODEL, mdd, mdd, mdd / 2);
        transposeW_kernel<<<gdd, tb>>>(Wv, wvt, D_MODEL, D_MODEL, mdd, mdd, mdd / 2);
        transposeW_kernel<<<gdd, tb>>>(Wo, wot, D_MODEL, D_MODEL, mdd, mdd, mdd / 2);
        size_t mdf = (size_t)D_MODEL * FF;
        transposeW_kernel<<<dim3(FF / 32, D_MODEL / 64, 4), tb>>>(W1, w1t, D_MODEL, FF, mdf, mdf, mdf / 2);
        transposeW_kernel<<<dim3(D_MODEL / 32, FF / 64, 4), tb>>>(W2, w2t, FF, D_MODEL, mdf, mdf, mdf / 2);
    }

    cudaMemcpyAsync(x, video, (size_t)SV * D_MODEL * 4, cudaMemcpyDeviceToDevice);
    cudaMemcpyAsync(x + (size_t)SV * D_MODEL, action, (size_t)SA * D_MODEL * 4, cudaMemcpyDeviceToDevice);

    const size_t AMID_D = (size_t)S_TOT * D_MODEL / 2;
    const size_t AMID_F = (size_t)S_TOT * FF / 2;

    for (int l = 0; l < NL; l++) {
        m6_kernel<<<48, 256>>>(mod, vtmod, atmod, m6, l);
        lnmod_kernel<<<S_TOT, 256>>>(x, (uint32_t*)a, m6, 0, 1);

        {
            GemmArgs ga = {};
            ga.Ah = (const uint32_t*)a; ga.amid = AMID_D;
            ga.Bth[0] = wqt + (size_t)l * D_MODEL * D_MODEL;
            ga.Bth[1] = wkt + (size_t)l * D_MODEL * D_MODEL;
            ga.Bth[2] = wvt + (size_t)l * D_MODEL * D_MODEL;
            ga.bmid = (size_t)D_MODEL * D_MODEL / 2;
            ga.westride = (size_t)NL * D_MODEL * D_MODEL;
            ga.bias[0] = bq + (size_t)l * D_MODEL;
            ga.bias[1] = bk + (size_t)l * D_MODEL;
            ga.bias[2] = bv + (size_t)l * D_MODEL;
            ga.bestride = (size_t)NL * D_MODEL;
            ga.C[0] = q; ga.C[1] = k; ga.C[2] = v;
            ga.K = D_MODEL; ga.ldc = D_MODEL;
            tgemm<0, 128><<<dim3(D_MODEL / 128, S_TOT / 128, 3), 256, SM128>>>(ga);
        }
        rmsrope_kernel<<<2 * S_TOT, 256>>>(q, k, gq, gk, vfreq, afreq, l);

        transpose_kernel<<<dim3(D_MODEL / 32, S_TOT / 32, 1), tb>>>(v, vt, S_TOT, D_MODEL, 0);
        flash_kernel<<<dim3(NH, S_TOT / 128), 256, SMFL>>>(q, k, vt, (uint32_t*)o);

        {
            GemmArgs ga = {};
            ga.Ah = (const uint32_t*)o; ga.amid = AMID_D;
            ga.Bth[0] = wot + (size_t)l * D_MODEL * D_MODEL;
            ga.bmid = (size_t)D_MODEL * D_MODEL / 2;
            ga.westride = (size_t)NL * D_MODEL * D_MODEL;
            ga.bias[0] = bo + (size_t)l * D_MODEL;
            ga.bestride = (size_t)NL * D_MODEL;
            ga.C[0] = x;
            ga.res = x; ga.m6 = m6; ga.gidx = 2;
            ga.K = D_MODEL; ga.ldc = D_MODEL;
            tgemm<2, 64><<<dim3(D_MODEL / 64, S_TOT / 128, 1), 128, SM64>>>(ga);
        }

        lnmod_kernel<<<S_TOT, 256>>>(x, (uint32_t*)a, m6, 3, 4);

        {
            GemmArgs ga = {};
            ga.Ah = (const uint32_t*)a; ga.amid = AMID_D;
            ga.Bth[0] = w1t + (size_t)l * D_MODEL * FF;
            ga.bmid = (size_t)D_MODEL * FF / 2;
            ga.westride = (size_t)NL * D_MODEL * FF;
            ga.bias[0] = b1 + (size_t)l * FF;
            ga.bestride = (size_t)NL * FF;
            ga.C[0] = hbuf; ga.cmid = AMID_F;
            ga.K = D_MODEL; ga.ldc = FF;
            tgemm<1, 128><<<dim3(FF / 128, S_TOT / 128, 1), 256, SM128>>>(ga);
        }
        {
            GemmArgs ga = {};
            ga.Ah = (const uint32_t*)hbuf; ga.amid = AMID_F;
            ga.Bth[0] = w2t + (size_t)l * FF * D_MODEL;
            ga.bmid = (size_t)FF * D_MODEL / 2;
            ga.westride = (size_t)NL * FF * D_MODEL;
            ga.bias[0] = b2 + (size_t)l * D_MODEL;
            ga.bestride = (size_t)NL * D_MODEL;
            ga.C[0] = x;
            ga.res = x; ga.m6 = m6; ga.gidx = 5;
            ga.K = FF; ga.ldc = D_MODEL;
            tgemm<2, 64><<<dim3(D_MODEL / 64, S_TOT / 128, 1), 128, SM64>>>(ga);
        }
    }

    cudaMemcpyAsync(out, x, (size_t)S_TOT * D_MODEL * 4, cudaMemcpyDeviceToDevice);
}

// round 17
// speedup vs baseline: 1.0242x; 1.0242x over previous
#include <cuda_runtime.h>
#include <cuda_bf16.h>
#include <math.h>
#include <stdint.h>

#define SV 2048
#define SA 512
#define S_TOT 2560
#define D_MODEL 1024
#define NH 16
#define DH 64
#define FF 4096
#define NL 2
#define LOG2E 1.4426950408889634f

__device__ __align__(16) float g_x[S_TOT * D_MODEL];
__device__ __align__(16) float g_a[S_TOT * D_MODEL];
__device__ __align__(16) float g_q[S_TOT * D_MODEL];
__device__ __align__(16) float g_k[S_TOT * D_MODEL];
__device__ __align__(16) float g_v[S_TOT * D_MODEL];
__device__ __align__(16) float g_vt[D_MODEL * S_TOT];
__device__ __align__(16) float g_o[S_TOT * D_MODEL];
__device__ __align__(16) float g_h[S_TOT * FF];
__device__ __align__(16) float g_m6[2 * 6 * D_MODEL];
__device__ __align__(16) uint32_t g_wqt[NL * 2 * D_MODEL * D_MODEL];
__device__ __align__(16) uint32_t g_wkt[NL * 2 * D_MODEL * D_MODEL];
__device__ __align__(16) uint32_t g_wvt[NL * 2 * D_MODEL * D_MODEL];
__device__ __align__(16) uint32_t g_wot[NL * 2 * D_MODEL * D_MODEL];
__device__ __align__(16) uint32_t g_w1t[(size_t)NL * 2 * D_MODEL * FF];
__device__ __align__(16) uint32_t g_w2t[(size_t)NL * 2 * FF * D_MODEL];

struct GemmArgs {
    const uint32_t* Ah;
    size_t amid;
    const uint32_t* Bth[3];
    size_t bmid;
    size_t westride;
    const float* bias[3];
    size_t bestride;
    void* C[3];
    size_t cmid;
    const float* res;
    const float* m6;
    int gidx;
    int K, ldc;
};

__device__ __forceinline__ void mma16(float* d, const uint32_t* a, const uint32_t* b) {
    asm volatile("mma.sync.aligned.m16n8k16.row.col.f32.bf16.bf16.f32 "
        "{%0,%1,%2,%3}, {%4,%5,%6,%7}, {%8,%9}, {%0,%1,%2,%3};"
        : "+f"(d[0]), "+f"(d[1]), "+f"(d[2]), "+f"(d[3])
        : "r"(a[0]), "r"(a[1]), "r"(a[2]), "r"(a[3]), "r"(b[0]), "r"(b[1]));
}
__device__ __forceinline__ void ldsm_x4(uint32_t* r, uint32_t addr) {
    asm volatile("ldmatrix.sync.aligned.m8n8.x4.shared.b16 {%0,%1,%2,%3}, [%4];"
        : "=r"(r[0]), "=r"(r[1]), "=r"(r[2]), "=r"(r[3]) : "r"(addr));
}
__device__ __forceinline__ void cpasync16(uint32_t saddr, const void* g) {
    asm volatile("cp.async.cg.shared.global [%0], [%1], 16;" :: "r"(saddr), "l"(g));
}
__device__ __forceinline__ void cp_commit() {
    asm volatile("cp.async.commit_group;");
}
__device__ __forceinline__ void cp_wait0() {
    asm volatile("cp.async.wait_group 0;");
}

__device__ __forceinline__ float fexp2(float x) {
    x = fmaxf(x, -126.f);
    float fl = floorf(x);
    float f = x - fl;
    float p = 1.54035304e-4f;
    p = fmaf(p, f, 1.33335581e-3f);
    p = fmaf(p, f, 9.61812911e-3f);
    p = fmaf(p, f, 5.55041087e-2f);
    p = fmaf(p, f, 2.40226507e-1f);
    p = fmaf(p, f, 6.93147181e-1f);
    p = fmaf(p, f, 1.0f);
    return p * __int_as_float(((int)fl + 127) << 23);
}

__device__ __forceinline__ uint32_t pack_bf2(float a, float b) {
    __nv_bfloat162 t = __floats2bfloat162_rn(a, b);
    return *(const uint32_t*)&t;
}
__device__ __forceinline__ void split2(float a, float b, uint32_t& hi, uint32_t& mid) {
    hi = pack_bf2(a, b);
    __nv_bfloat162* H = (__nv_bfloat162*)&hi;
    mid = pack_bf2(a - __bfloat162float(H->x), b - __bfloat162float(H->y));
}

__device__ __forceinline__ void blockReduce2(float& s, float& ss) {
    __shared__ float bufs[8], bufss[8];
    #pragma unroll
    for (int o = 16; o; o >>= 1) {
        s += __shfl_xor_sync(~0u, s, o); ss += __shfl_xor_sync(~0u, ss, o);
    }
    int w = threadIdx.x >> 5;
    if ((threadIdx.x & 31) == 0) { bufs[w] = s; bufss[w] = ss; }
    __syncthreads();
    if (threadIdx.x < 32) {
        s = (threadIdx.x < 8) ? bufs[threadIdx.x] : 0.f;
        ss = (threadIdx.x < 8) ? bufss[threadIdx.x] : 0.f;
        #pragma unroll
        for (int o = 4; o; o >>= 1) {
            s += __shfl_xor_sync(~0u, s, o); ss += __shfl_xor_sync(~0u, ss, o);
        }
        if (threadIdx.x == 0) { bufs[0] = s; bufss[0] = ss; }
    }
    __syncthreads();
    s = bufs[0]; ss = bufss[0];
}

__global__ void m6_kernel(const float* __restrict__ mod, const float* __restrict__ vt,
                          const float* __restrict__ at, float* __restrict__ m6, int l) {
    int idx = blockIdx.x * blockDim.x + threadIdx.x;
    if (idx >= 2 * 6 * D_MODEL) return;
    int e = idx / (6 * D_MODEL);
    int rem = idx % (6 * D_MODEL);
    m6[idx] = mod[((size_t)(e * NL + l) * 6) * D_MODEL + rem] + (e ? at[rem] : vt[rem]);
}

__global__ void __launch_bounds__(256) lnmod_kernel(const float* __restrict__ x, uint32_t* __restrict__ a,
                                                    const float* __restrict__ m6, int jsh, int jsc) {
    int row = blockIdx.x;
    int e = (row >= SV) ? 1 : 0;
    const float4* shv4 = (const float4*)(m6 + (size_t)(e * 6 + jsh) * D_MODEL);
    const float4* scv4 = (const float4*)(m6 + (size_t)(e * 6 + jsc) * D_MODEL);
    float4 v = ((const float4*)(x + (size_t)row * D_MODEL))[threadIdx.x];
    float s = v.x + v.y + v.z + v.w;
    float ss = v.x * v.x + v.y * v.y + v.z * v.z + v.w * v.w;
    blockReduce2(s, ss);
    float mu = s * (1.f / D_MODEL);
    float var = ss * (1.f / D_MODEL) - mu * mu;
    float r = rsqrtf(var + 1e-6f);
    float4 sh = shv4[threadIdx.x], sc = scv4[threadIdx.x];
    float o0 = (v.x - mu) * r * (1.f + sc.x) + sh.x;
    float o1 = (v.y - mu) * r * (1.f + sc.y) + sh.y;
    float o2 = (v.z - mu) * r * (1.f + sc.z) + sh.z;
    float o3 = (v.w - mu) * r * (1.f + sc.w) + sh.w;
    uint32_t h01, m01, h23, m23;
    split2(o0, o1, h01, m01);
    split2(o2, o3, h23, m23);
    const size_t MID = (size_t)S_TOT * D_MODEL / 2;
    size_t w = (size_t)row * (D_MODEL / 2) + threadIdx.x * 2;
    a[w] = h01; a[w + 1] = h23;
    a[MID + w] = m01; a[MID + w + 1] = m23;
}

__global__ void __launch_bounds__(256) rmsrope_kernel(float* __restrict__ qb, float* __restrict__ kb,
                                                      const float* __restrict__ gq, const float* __restrict__ gk,
                                                      const float* __restrict__ vfreq, const float* __restrict__ afreq,
                                                      int l) {
    int bid = blockIdx.x;
    int isk = (bid >= S_TOT);
    int row = isk ? bid - S_TOT : bid;
    float* q = isk ? kb : qb;
    const float* gbase = isk ? gk : gq;
    int e = (row >= SV) ? 1 : 0;
    int pos = e ? row - SV : row;
    const float* fr = e ? (afreq + (size_t)pos * (DH / 2)) : (vfreq + (size_t)pos * (DH / 2));
    const float* g = gbase + (size_t)(e * NL + l) * D_MODEL;
    float4 v = ((const float4*)(q + (size_t)row * D_MODEL))[threadIdx.x];
    float ss = v.x * v.x + v.y * v.y + v.z * v.z + v.w * v.w, dummy = 0.f;
    blockReduce2(ss, dummy);
    float r = rsqrtf(ss * (1.f / D_MODEL) + 1e-6f);
    float4 gv = ((const float4*)g)[threadIdx.x];
    int d0 = threadIdx.x * 4;
    int j0 = (d0 & (DH - 1)) >> 1, j1 = j0 + 1;
    float c0 = cosf(fr[j0]), s0 = sinf(fr[j0]);
    float c1 = cosf(fr[j1]), s1 = sinf(fr[j1]);
    float xe0 = v.x * r * gv.x, xo0 = v.y * r * gv.y;
    float xe1 = v.z * r * gv.z, xo1 = v.w * r * gv.w;
    float4 o;
    o.x = xe0 * c0 - xo0 * s0; o.y = xe0 * s0 + xo0 * c0;
    o.z = xe1 * c1 - xo1 * s1; o.w = xe1 * s1 + xo1 * c1;
    ((float4*)(q + (size_t)row * D_MODEL))[threadIdx.x] = o;
}

__global__ void __launch_bounds__(256) transpose_kernel(const float* __restrict__ src, float* __restrict__ dst,
                                                        int R, int C, size_t msize) {
    __shared__ float t[32][33];
    src += blockIdx.z * msize;
    dst += blockIdx.z * msize;
    int bx = blockIdx.x * 32, by = blockIdx.y * 32;
    for (int i = threadIdx.y; i < 32; i += 8)
        t[i][threadIdx.x] = src[(size_t)(by + i) * C + bx + threadIdx.x];
    __syncthreads();
    for (int i = threadIdx.y; i < 32; i += 8)
        dst[(size_t)(bx + i) * R + by + threadIdx.x] = t[threadIdx.x][i];
}

// transpose + bf16 split, coalesced stores: tile 64(R) x 32(C)
__global__ void __launch_bounds__(256) transposeW_kernel(const float* __restrict__ src, uint32_t* __restrict__ dst,
                                                         int R, int C, size_t min_, size_t mout, size_t midoff) {
    __shared__ float t[64][33];
    src += blockIdx.z * min_;
    dst += blockIdx.z * mout;
    int bx = blockIdx.x * 32, by = blockIdx.y * 64;
    int tx = threadIdx.x, ty = threadIdx.y;
    #pragma unroll
    for (int i = ty; i < 64; i += 8)
        t[i][tx] = src[(size_t)(by + i) * C + bx + tx];
    __syncthreads();
    #pragma unroll
    for (int i = ty; i < 32; i += 8) {
        float v0 = t[2 * tx][i], v1 = t[2 * tx + 1][i];
        uint32_t hi, mid;
        split2(v0, v1, hi, mid);
        size_t w = (size_t)(bx + i) * (R >> 1) + (by >> 1) + tx;
        dst[w] = hi;
        dst[midoff + w] = mid;
    }
}

// ---------------- flash attention (R15-proven: 64-row Q tile, static smem) ----------------
#define FST 36
__global__ void __launch_bounds__(128) flash_kernel(
    const float* __restrict__ Q, const float* __restrict__ K,
    const float* __restrict__ Vt, uint32_t* __restrict__ O) {
    __shared__ __align__(16) uint32_t sQh[64 * FST], sQm[64 * FST], sKh[64 * FST], sKm[64 * FST],
                                      sVh[64 * FST], sVm[64 * FST];
    int h = blockIdx.x;
    int q0 = blockIdx.y * 64;
    int tid = threadIdx.x, wid = tid >> 5, lane = tid & 31;
    int r = lane >> 2, cq = lane & 3;

    uint32_t bQh = (uint32_t)__cvta_generic_to_shared(sQh);
    uint32_t bQm = (uint32_t)__cvta_generic_to_shared(sQm);
    uint32_t bKh = (uint32_t)__cvta_generic_to_shared(sKh);
    uint32_t bKm = (uint32_t)__cvta_generic_to_shared(sKm);
    uint32_t bVh = (uint32_t)__cvta_generic_to_shared(sVh);
    uint32_t bVm = (uint32_t)__cvta_generic_to_shared(sVm);
    uint32_t aoff = ((wid * 16 + (lane & 15)) * FST + ((lane >> 4) << 2)) * 4;
    uint32_t boff = ((((lane & 7) + ((lane >> 4) << 3)) * FST) + (((lane >> 3) & 1) << 2)) * 4;

    #pragma unroll
    for (int i = 0; i < 8; i++) {
        int idx = tid + i * 128;
        int row = idx >> 4, c4 = idx & 15;
        float4 f = *(const float4*)(Q + (size_t)(q0 + row) * D_MODEL + h * DH + c4 * 4);
        f.x *= 0.125f; f.y *= 0.125f; f.z *= 0.125f; f.w *= 0.125f;
        uint32_t h01, m01, h23, m23;
        split2(f.x, f.y, h01, m01);
        split2(f.z, f.w, h23, m23);
        int o2 = row * FST + c4 * 2;
        sQh[o2] = h01; sQh[o2 + 1] = h23;
        sQm[o2] = m01; sQm[o2 + 1] = m23;
    }

    int row0 = q0 + wid * 16 + r, row1 = row0 + 8;
    float mx0 = -1e30f, mx1 = -1e30f, l0 = 0.f, l1 = 0.f;
    float oa[8][4];
    #pragma unroll
    for (int j = 0; j < 8; j++)
        #pragma unroll
        for (int t = 0; t < 4; t++) oa[j][t] = 0.f;

    int kend = (q0 < SV) ? SV : (q0 + 64);
    for (int kb = 0; kb < kend; kb += 64) {
        __syncthreads();
        #pragma unroll
        for (int i = 0; i < 16; i++) {
            int idx = tid + i * 128;
            const float* src;
            uint32_t *dh_, *dm_;
            int row, c4;
            if (idx < 1024) {
                row = idx >> 4; c4 = idx & 15;
                src = K + (size_t)(kb + row) * D_MODEL + h * DH + c4 * 4;
                dh_ = sKh; dm_ = sKm;
            } else {
                int jj = idx - 1024;
                row = jj >> 4; c4 = jj & 15;
                src = Vt + (size_t)(h * DH + row) * S_TOT + kb + c4 * 4;
                dh_ = sVh; dm_ = sVm;
            }
            float4 f = *(const float4*)src;
            uint32_t h01, m01, h23, m23;
            split2(f.x, f.y, h01, m01);
            split2(f.z, f.w, h23, m23);
            int o2 = row * FST + c4 * 2;
            dh_[o2] = h01; dh_[o2 + 1] = h23;
            dm_[o2] = m01; dm_[o2 + 1] = m23;
        }
        __syncthreads();

        float s[8][4];
        #pragma unroll
        for (int j = 0; j < 8; j++)
            #pragma unroll
            for (int t = 0; t < 4; t++) s[j][t] = 0.f;
        #pragma unroll
        for (int k16 = 0; k16 < 4; k16++) {
            int kwB = k16 * 32;
            uint32_t ah[4], am[4];
            ldsm_x4(ah, bQh + aoff + kwB);
            ldsm_x4(am, bQm + aoff + kwB);
            #pragma unroll
            for (int jp = 0; jp < 8; jp += 2) {
                uint32_t bh4[4], bm4[4];
                ldsm_x4(bh4, bKh + boff + jp * 8 * FST * 4 + kwB);
                ldsm_x4(bm4, bKm + boff + jp * 8 * FST * 4 + kwB);
                mma16(s[jp], ah, bh4);
                mma16(s[jp], am, bh4);
                mma16(s[jp], ah, bm4);
                mma16(s[jp + 1], ah, bh4 + 2);
                mma16(s[jp + 1], am, bh4 + 2);
                mma16(s[jp + 1], ah, bm4 + 2);
            }
        }
        if (kb >= SV) {
            #pragma unroll
            for (int j = 0; j < 8; j++) {
                int key = kb + j * 8 + 2 * cq;
                if (key > row0) s[j][0] = -1e30f;
                if (key + 1 > row0) s[j][1] = -1e30f;
                if (key > row1) s[j][2] = -1e30f;
                if (key + 1 > row1) s[j][3] = -1e30f;
            }
        }
        float tm0 = -1e30f, tm1 = -1e30f;
        #pragma unroll
        for (int j = 0; j < 8; j++) {
            tm0 = fmaxf(tm0, fmaxf(s[j][0], s[j][1]));
            tm1 = fmaxf(tm1, fmaxf(s[j][2], s[j][3]));
        }
        tm0 = fmaxf(tm0, __shfl_xor_sync(~0u, tm0, 1));
        tm0 = fmaxf(tm0, __shfl_xor_sync(~0u, tm0, 2));
        tm1 = fmaxf(tm1, __shfl_xor_sync(~0u, tm1, 1));
        tm1 = fmaxf(tm1, __shfl_xor_sync(~0u, tm1, 2));
        float mn0 = fmaxf(mx0, tm0), mn1 = fmaxf(mx1, tm1);
        float corr0 = fexp2((mx0 - mn0) * LOG2E);
        float corr1 = fexp2((mx1 - mn1) * LOG2E);
        mx0 = mn0; mx1 = mn1;
        float ps0 = 0.f, ps1 = 0.f;
        #pragma unroll
        for (int j = 0; j < 8; j++) {
            s[j][0] = fexp2((s[j][0] - mn0) * LOG2E);
            s[j][1] = fexp2((s[j][1] - mn0) * LOG2E);
            s[j][2] = fexp2((s[j][2] - mn1) * LOG2E);
            s[j][3] = fexp2((s[j][3] - mn1) * LOG2E);
            ps0 += s[j][0] + s[j][1];
            ps1 += s[j][2] + s[j][3];
        }
        ps0 += __shfl_xor_sync(~0u, ps0, 1); ps0 += __shfl_xor_sync(~0u, ps0, 2);
        ps1 += __shfl_xor_sync(~0u, ps1, 1); ps1 += __shfl_xor_sync(~0u, ps1, 2);
        l0 = l0 * corr0 + ps0;
        l1 = l1 * corr1 + ps1;
        #pragma unroll
        for (int j = 0; j < 8; j++) {
            oa[j][0] *= corr0; oa[j][1] *= corr0;
            oa[j][2] *= corr1; oa[j][3] *= corr1;
        }
        #pragma unroll
        for (int j2 = 0; j2 < 4; j2++) {
            int t0 = 2 * j2, t1 = 2 * j2 + 1;
            uint32_t pah[4], pam[4];
            split2(s[t0][0], s[t0][1], pah[0], pam[0]);
            split2(s[t0][2], s[t0][3], pah[1], pam[1]);
            split2(s[t1][0], s[t1][1], pah[2], pam[2]);
            split2(s[t1][2], s[t1][3], pah[3], pam[3]);
            int kwB = j2 * 32;
            #pragma unroll
            for (int jp = 0; jp < 8; jp += 2) {
                uint32_t bh4[4], bm4[4];
                ldsm_x4(bh4, bVh + boff + jp * 8 * FST * 4 + kwB);
                ldsm_x4(bm4, bVm + boff + jp * 8 * FST * 4 + kwB);
                mma16(oa[jp], pah, bh4);
                mma16(oa[jp], pam, bh4);
                mma16(oa[jp], pah, bm4);
                mma16(oa[jp + 1], pah, bh4 + 2);
                mma16(oa[jp + 1], pam, bh4 + 2);
                mma16(oa[jp + 1], pah, bm4 + 2);
            }
        }
    }

    const size_t OMID = (size_t)S_TOT * D_MODEL / 2;
    float inv0 = 1.f / l0, inv1 = 1.f / l1;
    #pragma unroll
    for (int jn = 0; jn < 8; jn++) {
        int col = h * DH + jn * 8 + cq * 2;
        uint32_t hi0, mi0, hi1, mi1;
        split2(oa[jn][0] * inv0, oa[jn][1] * inv0, hi0, mi0);
        split2(oa[jn][2] * inv1, oa[jn][3] * inv1, hi1, mi1);
        size_t w0 = (size_t)row0 * (D_MODEL / 2) + (col >> 1);
        size_t w1 = (size_t)row1 * (D_MODEL / 2) + (col >> 1);
        O[w0] = hi0; O[OMID + w0] = mi0;
        O[w1] = hi1; O[OMID + w1] = mi1;
    }
}

// ---------- merged GEMM: pre-split inputs, cp.async staging, LDSM fragments ----------
template <int EPI, int BN>
__global__ void __launch_bounds__((BN == 128) ? 256 : 128) tgemm(GemmArgs args) {
    constexpr int THREADS = (BN == 128) ? 256 : 128;
    constexpr int WX = BN / 32;
    constexpr int AHI = 0, AMI = 2560, BHIo = 5120, BMIo = 5120 + BN * 20;
    constexpr int STG = 5120 + BN * 40;
    constexpr int NPF = (1024 + BN * 8) / THREADS;

    extern __shared__ uint32_t smw[];
    int tid = threadIdx.x;
    int wid = tid >> 5, lane = tid & 31;
    int wy = wid / WX, wx = wid % WX;
    int r = lane >> 2, cq = lane & 3;
    int z = blockIdx.z;
    int e = (blockIdx.y * 128 >= SV) ? 1 : 0;
    int K = args.K;
    int ldw = K >> 1;

    uint32_t sbase = (uint32_t)__cvta_generic_to_shared(smw);
    uint32_t aoff = ((wy * 64 + (lane & 15)) * 20 + ((lane >> 4) << 2)) * 4;
    uint32_t boff = ((wx * 32 + (lane & 7) + ((lane >> 4) << 3)) * 20 + (((lane >> 3) & 1) << 2)) * 4;

    const uint32_t* Ahi = args.Ah + (size_t)blockIdx.y * 128 * ldw;
    const uint32_t* Bhi = args.Bth[z] + (size_t)e * args.westride + (size_t)blockIdx.x * BN * ldw;
    size_t amid = args.amid, bmid = args.bmid;
    const float* bias = args.bias[z] + (size_t)e * args.bestride;
    const float* gate = (EPI == 2) ? (args.m6 + (size_t)(e * 6 + args.gidx) * D_MODEL) : nullptr;
    int ldc = args.ldc;

    float acc[4][4][4];
    #pragma unroll
    for (int i = 0; i < 4; i++)
        #pragma unroll
        for (int j = 0; j < 4; j++)
            #pragma unroll
            for (int t = 0; t < 4; t++) acc[i][j][t] = 0.f;

    auto issueLoads = [&](int c, int s) {
        uint32_t base = sbase + s * STG * 4;
        #pragma unroll
        for (int t = 0; t < NPF; t++) {
            int idx = tid + t * THREADS;
            const uint32_t* src;
            int plane, i2;
            if (idx < 1024) {
                int p = idx >> 9;
                i2 = idx & 511;
                src = Ahi + (p ? amid : 0) + (size_t)(i2 >> 2) * ldw + c * 16 + (i2 & 3) * 4;
                plane = p ? AMI : AHI;
            } else {
                int bidx = idx - 1024;
                int p = (bidx >= BN * 4) ? 1 : 0;
                i2 = bidx - p * BN * 4;
                src = Bhi + (p ? bmid : 0) + (size_t)(i2 >> 2) * ldw + c * 16 + (i2 & 3) * 4;
                plane = p ? BMIo : BHIo;
            }
            cpasync16(base + (plane + (i2 >> 2) * 20 + (i2 & 3) * 4) * 4, src);
        }
        cp_commit();
    };
    auto compute = [&](int s) {
        uint32_t stb = sbase + s * STG * 4;
        #pragma unroll
        for (int k16 = 0; k16 < 2; k16++) {
            int kwB = k16 * 32;
            uint32_t ah[4][4], am[4][4], bh[2][4], bm[2][4];
            #pragma unroll
            for (int i = 0; i < 4; i++) {
                ldsm_x4(ah[i], stb + aoff + i * 16 * 20 * 4 + kwB);
                ldsm_x4(am[i], stb + AMI * 4 + aoff + i * 16 * 20 * 4 + kwB);
            }
            #pragma unroll
            for (int jp = 0; jp < 2; jp++) {
                ldsm_x4(bh[jp], stb + BHIo * 4 + boff + jp * 16 * 20 * 4 + kwB);
                ldsm_x4(bm[jp], stb + BMIo * 4 + boff + jp * 16 * 20 * 4 + kwB);
            }
            #pragma unroll
            for (int i = 0; i < 4; i++)
                #pragma unroll
                for (int j = 0; j < 4; j++)
                    mma16(acc[i][j], ah[i], bh[j >> 1] + (j & 1) * 2);
            #pragma unroll
            for (int i = 0; i < 4; i++)
                #pragma unroll
                for (int j = 0; j < 4; j++)
                    mma16(acc[i][j], am[i], bh[j >> 1] + (j & 1) * 2);
            #pragma unroll
            for (int i = 0; i < 4; i++)
                #pragma unroll
                for (int j = 0; j < 4; j++)
                    mma16(acc[i][j], ah[i], bm[j >> 1] + (j & 1) * 2);
        }
    };

    issueLoads(0, 0);
    cp_wait0();
    __syncthreads();
    int NC = K >> 5;
    for (int c = 0; c < NC; c++) {
        if (c + 1 < NC) issueLoads(c + 1, (c + 1) & 1);
        compute(c & 1);
        if (c + 1 < NC) cp_wait0();
        __syncthreads();
    }

    int rowb = blockIdx.y * 128 + wy * 64;
    int colb = blockIdx.x * BN + wx * 32;
    #pragma unroll
    for (int i = 0; i < 4; i++) {
        #pragma unroll
        for (int j = 0; j < 4; j++) {
            int col = colb + j * 8 + cq * 2;
            #pragma unroll
            for (int h = 0; h < 2; h++) {
                int row = rowb + i * 16 + r + h * 8;
                float v0 = acc[i][j][h * 2], v1 = acc[i][j][h * 2 + 1];
                v0 += bias[col]; v1 += bias[col + 1];
                if (EPI == 1) {
                    float t0 = v0, t1 = v1;
                    v0 = 0.5f * t0 * (1.f + tanhf(0.7978845608028654f * (t0 + 0.044715f * t0 * t0 * t0)));
                    v1 = 0.5f * t1 * (1.f + tanhf(0.7978845608028654f * (t1 + 0.044715f * t1 * t1 * t1)));
                    uint32_t hi, mid;
                    split2(v0, v1, hi, mid);
                    uint32_t* Ch = (uint32_t*)args.C[z];
                    size_t w = (size_t)row * (ldc >> 1) + (col >> 1);
                    Ch[w] = hi;
                    Ch[args.cmid + w] = mid;
                } else {
                    if (EPI == 2) {
                        float2 rv = *(const float2*)(args.res + (size_t)row * ldc + col);
                        v0 = rv.x + gate[col] * v0;
                        v1 = rv.y + gate[col + 1] * v1;
                    }
                    float2 ov; ov.x = v0; ov.y = v1;
                    *(float2*)((float*)args.C[z] + (size_t)row * ldc + col) = ov;
                }
            }
        }
    }
}

extern "C" void kernel_launch(void* const* d_in, const int* in_sizes, int n_in,
                              void* d_out, int out_size) {
    const float* video = (const float*)d_in[0];
    const float* action = (const float*)d_in[1];
    const float* vfreq = (const float*)d_in[2];
    const float* afreq = (const float*)d_in[3];
    const float* vtmod = (const float*)d_in[4];
    const float* atmod = (const float*)d_in[5];
    const float* Wq = (const float*)d_in[6];
    const float* Wk = (const float*)d_in[7];
    const float* Wv = (const float*)d_in[8];
    const float* Wo = (const float*)d_in[9];
    const float* bq = (const float*)d_in[10];
    const float* bk = (const float*)d_in[11];
    const float* bv = (const float*)d_in[12];
    const float* bo = (const float*)d_in[13];
    const float* gq = (const float*)d_in[14];
    const float* gk = (const float*)d_in[15];
    const float* mod = (const float*)d_in[16];
    const float* W1 = (const float*)d_in[17];
    const float* b1 = (const float*)d_in[18];
    const float* W2 = (const float*)d_in[19];
    const float* b2 = (const float*)d_in[20];
    float* out = (float*)d_out;

    float *x, *a, *q, *k, *v, *vt, *o, *hbuf, *m6;
    uint32_t *wqt, *wkt, *wvt, *wot, *w1t, *w2t;
    cudaGetSymbolAddress((void**)&x, g_x);
    cudaGetSymbolAddress((void**)&a, g_a);
    cudaGetSymbolAddress((void**)&q, g_q);
    cudaGetSymbolAddress((void**)&k, g_k);
    cudaGetSymbolAddress((void**)&v, g_v);
    cudaGetSymbolAddress((void**)&vt, g_vt);
    cudaGetSymbolAddress((void**)&o, g_o);
    cudaGetSymbolAddress((void**)&hbuf, g_h);
    cudaGetSymbolAddress((void**)&m6, g_m6);
    cudaGetSymbolAddress((void**)&wqt, g_wqt);
    cudaGetSymbolAddress((void**)&wkt, g_wkt);
    cudaGetSymbolAddress((void**)&wvt, g_wvt);
    cudaGetSymbolAddress((void**)&wot, g_wot);
    cudaGetSymbolAddress((void**)&w1t, g_w1t);
    cudaGetSymbolAddress((void**)&w2t, g_w2t);

    const int SM128 = (5120 + 128 * 40) * 2 * 4;
    const int SM64  = (5120 + 64 * 40) * 2 * 4;
    cudaFuncSetAttribute(tgemm<0, 128>, cudaFuncAttributeMaxDynamicSharedMemorySize, SM128);
    cudaFuncSetAttribute(tgemm<1, 128>, cudaFuncAttributeMaxDynamicSharedMemorySize, SM128);
    cudaFuncSetAttribute(tgemm<2, 64>, cudaFuncAttributeMaxDynamicSharedMemorySize, SM64);

    dim3 tb(32, 8);
    {
        size_t mdd = (size_t)D_MODEL * D_MODEL;
        dim3 gdd(D_MODEL / 32, D_MODEL / 64, 4);
        transposeW_kernel<<<gdd, tb>>>(Wq, wqt, D_MODEL, D_MODEL, mdd, mdd, mdd / 2);
        transposeW_kernel<<<gdd, tb>>>(Wk, wkt, D_MODEL, D_MODEL, mdd, mdd, mdd / 2);
        transposeW_kernel<<<gdd, tb>>>(Wv, wvt, D_MODEL, D_MODEL, mdd, mdd, mdd / 2);
        transposeW_kernel<<<gdd, tb>>>(Wo, wot, D_MODEL, D_MODEL, mdd, mdd, mdd / 2);
        size_t mdf = (size_t)D_MODEL * FF;
        transposeW_kernel<<<dim3(FF / 32, D_MODEL / 64, 4), tb>>>(W1, w1t, D_MODEL, FF, mdf, mdf, mdf / 2);
        transposeW_kernel<<<dim3(D_MODEL / 32, FF / 64, 4), tb>>>(W2, w2t, FF, D_MODEL, mdf, mdf, mdf / 2);
    }

    cudaMemcpyAsync(x, video, (size_t)SV * D_MODEL * 4, cudaMemcpyDeviceToDevice);
    cudaMemcpyAsync(x + (size_t)SV * D_MODEL, action, (size_t)SA * D_MODEL * 4, cudaMemcpyDeviceToDevice);

    const size_t AMID_D = (size_t)S_TOT * D_MODEL / 2;
    const size_t AMID_F = (size_t)S_TOT * FF / 2;

    for (int l = 0; l < NL; l++) {
        m6_kernel<<<48, 256>>>(mod, vtmod, atmod, m6, l);
        lnmod_kernel<<<S_TOT, 256>>>(x, (uint32_t*)a, m6, 0, 1);

        {
            GemmArgs ga = {};
            ga.Ah = (const uint32_t*)a; ga.amid = AMID_D;
            ga.Bth[0] = wqt + (size_t)l * D_MODEL * D_MODEL;
            ga.Bth[1] = wkt + (size_t)l * D_MODEL * D_MODEL;
            ga.Bth[2] = wvt + (size_t)l * D_MODEL * D_MODEL;
            ga.bmid = (size_t)D_MODEL * D_MODEL / 2;
            ga.westride = (size_t)NL * D_MODEL * D_MODEL;
            ga.bias[0] = bq + (size_t)l * D_MODEL;
            ga.bias[1] = bk + (size_t)l * D_MODEL;
            ga.bias[2] = bv + (size_t)l * D_MODEL;
            ga.bestride = (size_t)NL * D_MODEL;
            ga.C[0] = q; ga.C[1] = k; ga.C[2] = v;
            ga.K = D_MODEL; ga.ldc = D_MODEL;
            tgemm<0, 128><<<dim3(D_MODEL / 128, S_TOT / 128, 3), 256, SM128>>>(ga);
        }
        rmsrope_kernel<<<2 * S_TOT, 256>>>(q, k, gq, gk, vfreq, afreq, l);

        transpose_kernel<<<dim3(D_MODEL / 32, S_TOT / 32, 1), tb>>>(v, vt, S_TOT, D_MODEL, 0);
        flash_kernel<<<dim3(NH, S_TOT / 64), 128>>>(q, k, vt, (uint32_t*)o);

        {
            GemmArgs ga = {};
            ga.Ah = (const uint32_t*)o; ga.amid = AMID_D;
            ga.Bth[0] = wot + (size_t)l * D_MODEL * D_MODEL;
            ga.bmid = (size_t)D_MODEL * D_MODEL / 2;
            ga.westride = (size_t)NL * D_MODEL * D_MODEL;
            ga.bias[0] = bo + (size_t)l * D_MODEL;
            ga.bestride = (size_t)NL * D_MODEL;
            ga.C[0] = x;
            ga.res = x; ga.m6 = m6; ga.gidx = 2;
            ga.K = D_MODEL; ga.ldc = D_MODEL;
            tgemm<2, 64><<<dim3(D_MODEL / 64, S_TOT / 128, 1), 128, SM64>>>(ga);
        }

        lnmod_kernel<<<S_TOT, 256>>>(x, (uint32_t*)a, m6, 3, 4);

        {
            GemmArgs ga = {};
            ga.Ah = (const uint32_t*)a; ga.amid = AMID_D;
            ga.Bth[0] = w1t + (size_t)l * D_MODEL * FF;
            ga.bmid = (size_t)D_MODEL * FF / 2;
            ga.westride = (size_t)NL * D_MODEL * FF;
            ga.bias[0] = b1 + (size_t)l * FF;
            ga.bestride = (size_t)NL * FF;
            ga.C[0] = hbuf; ga.cmid = AMID_F;
            ga.K = D_MODEL; ga.ldc = FF;
            tgemm<1, 128><<<dim3(FF / 128, S_TOT / 128, 1), 256, SM128>>>(ga);
        }
        {
            GemmArgs ga = {};
            ga.Ah = (const uint32_t*)hbuf; ga.amid = AMID_F;
            ga.Bth[0] = w2t + (size_t)l * FF * D_MODEL;
            ga.bmid = (size_t)FF * D_MODEL / 2;
            ga.westride = (size_t)NL * FF * D_MODEL;
            ga.bias[0] = b2 + (size_t)l * D_MODEL;
            ga.bestride = (size_t)NL * D_MODEL;
            ga.C[0] = x;
            ga.res = x; ga.m6 = m6; ga.gidx = 5;
            ga.K = FF; ga.ldc = D_MODEL;
            tgemm<2, 64><<<dim3(D_MODEL / 64, S_TOT / 128, 1), 128, SM64>>>(ga);
        }
    }

    cudaMemcpyAsync(out, x, (size_t)S_TOT * D_MODEL * 4, cudaMemcpyDeviceToDevice);
}